// round 15
// baseline (speedup 1.0000x reference)
#include <cuda_runtime.h>
#include <math_constants.h>

#define EPSY 1e-6f
#define NB 150
#define NBP 152              // padded: each sub-lane scans exactly 38
#define NCLS 20
#define INV_PI2 0.405284734569351f   // 4/pi^2
#define THIRD 0.3333333333333333f

// ---- fixed problem shape ----
#define BATCH 4
#define PB0 17328   // 76*76*3
#define PB1 4332    // 38*38*3
#define PB2 1083    // 19*19*3
#define SPLIT 4
#define APB 64              // anchors per block (256 threads / SPLIT)
#define NBLK0 271           // ceil(PB0/64)
#define NBLK1 68
#define NBLK2 17
#define CUM1 (NBLK0*BATCH)                 // 1084
#define CUM2 (CUM1 + NBLK1*BATCH)          // 1356
#define TOTAL_BLOCKS (CUM2 + NBLK2*BATCH)  // 1424
#define CHUNK 38            // NBP / SPLIT

__device__ __forceinline__ float softplusf(float x) {
    return (x > 0.0f) ? (x + log1pf(expf(-x))) : log1pf(expf(x));
}

__device__ __forceinline__ void box_corners(
    float x, float y, float w, float h,
    float& lx, float& ly, float& hx, float& hy, float& ar)
{
    float ltx = x - w * 0.5f, rbx = x + w * 0.5f;
    float lty = y - h * 0.5f, rby = y + h * 0.5f;
    lx = fminf(ltx, rbx); hx = fmaxf(ltx, rbx);
    ly = fminf(lty, rby); hy = fmaxf(lty, rby);
    ar = (hx - lx) * (hy - ly);
}

// Full CIoU (reference-faithful, fast divides).
__device__ __forceinline__ float ciou_full(
    float alx, float aly, float ahx, float ahy, float aar, float acx, float acy, float aat,
    float blx, float bly, float bhx, float bhy, float bar, float bcx, float bcy, float bat)
{
    float iw = fminf(ahx, bhx) - fmaxf(alx, blx); iw = fmaxf(iw, 0.0f);
    float ih = fminf(ahy, bhy) - fmaxf(aly, bly); ih = fmaxf(ih, 0.0f);
    float inter = iw * ih;
    float uni   = aar + bar - inter;
    float iou   = __fdividef(inter, fmaxf(uni, EPSY));
    float ow = fmaxf(ahx, bhx) - fminf(alx, blx);
    float oh = fmaxf(ahy, bhy) - fminf(aly, bly);
    float c2 = fmaxf(ow * ow + oh * oh, EPSY);
    float dx = acx - bcx, dy = acy - bcy;
    float u  = __fdividef(dx * dx + dy * dy, c2);
    float dv = bat - aat;
    float v  = INV_PI2 * dv * dv;
    float alpha = __fdividef(v, fmaxf(1.0f - iou + v, EPSY));
    return iou - (u + alpha * v);
}

__global__ __launch_bounds__(256)
void yolo_fused_kernel(
    const float* __restrict__ p0,  const float* __restrict__ p1,  const float* __restrict__ p2,
    const float* __restrict__ pd0, const float* __restrict__ pd1, const float* __restrict__ pd2,
    const float* __restrict__ lb0, const float* __restrict__ lb1, const float* __restrict__ lb2,
    const float* __restrict__ bb0, const float* __restrict__ bb1, const float* __restrict__ bb2,
    float inv_img2, float inv_bs,
    float* __restrict__ out)
{
    __shared__ float4 s_geo[NBP];   // lx, ly, hx, hy
    __shared__ float  s_b3[NBP];    // area/3  (pad: +huge -> never hits)
    __shared__ float4 s_aux[NBP];   // cx, cy, atan(w/h), area
    __shared__ float  s_pd[APB * 25];   // staged pd rows (coalesced copy)
    __shared__ float  s_p [APB * 25];   // staged p rows
    __shared__ float  s_lb[APB * 26];   // staged label rows
    __shared__ float  s_red[3][8];

    // ---- decode block -> (layer segment, batch, block-within-batch) ----
    int bid = blockIdx.x;
    int rem, nb, per_batch;
    const float *p, *pd, *lb, *bb;
    if (bid < CUM1)      { rem = bid;        nb = NBLK0; per_batch = PB0; p = p0; pd = pd0; lb = lb0; bb = bb0; }
    else if (bid < CUM2) { rem = bid - CUM1; nb = NBLK1; per_batch = PB1; p = p1; pd = pd1; lb = lb1; bb = bb1; }
    else                 { rem = bid - CUM2; nb = NBLK2; per_batch = PB2; p = p2; pd = pd2; lb = lb2; bb = bb2; }
    int b   = rem / nb;
    int blk = rem - b * nb;

    // ---- coalesced staging of this block's anchor rows ----
    // 64 contiguous rows each of pd/p (25 fl) and label (26 fl): flat scalar
    // copies -> perfectly coalesced 128B/warp, ~19 independent LDGs/thread.
    {
        const int a0    = blk * APB;
        const int count = min(APB, per_batch - a0);
        const size_t base = (size_t)b * per_batch + a0;
        const float* pd_src = pd + base * 25;
        const float* p_src  = p  + base * 25;
        const float* lb_src = lb + base * 26;
        const int n25 = count * 25;
        const int n26 = count * 26;
        for (int j = threadIdx.x; j < n25; j += 256) {
            s_pd[j] = pd_src[j];
            s_p[j]  = p_src[j];
        }
        for (int j = threadIdx.x; j < n26; j += 256)
            s_lb[j] = lb_src[j];
    }

    // ---- stage this batch's bboxes (preprocessed, padded) in smem ----
    for (int j = threadIdx.x; j < NBP; j += 256) {
        if (j < NB) {
            const float* q = bb + ((size_t)b * NB + j) * 4;
            float x = q[0], y = q[1], w = q[2], h = q[3];
            float lx, ly, hx, hy, ar;
            box_corners(x, y, w, h, lx, ly, hx, hy, ar);
            s_geo[j] = make_float4(lx, ly, hx, hy);
            s_b3[j]  = ar * THIRD;
            s_aux[j] = make_float4(x, y, atanf(__fdividef(w, fmaxf(h, EPSY))), ar);
        } else {
            s_geo[j] = make_float4(0.0f, 0.0f, 0.0f, 0.0f);
            s_b3[j]  = 3.0e30f;
            s_aux[j] = make_float4(0.0f, 0.0f, 0.0f, 1.0f);
        }
    }
    __syncthreads();

    const int sub = threadIdx.x & (SPLIT - 1);
    const int la  = threadIdx.x >> 2;           // local anchor 0..63
    const int j0  = sub * CHUNK;
    const unsigned full = 0xFFFFFFFFu;

    const int i = blk * APB + la;
    const bool valid = (i < per_batch);

    float sum_ciou = 0.0f, sum_conf = 0.0f, sum_cls = 0.0f;
    float m = -CUDART_INF_F;

    float alx, aly, ahx, ahy, aar, ax, ay, aw, ah;

    if (valid) {
        ax = s_pd[la * 25 + 0]; ay = s_pd[la * 25 + 1];
        aw = s_pd[la * 25 + 2]; ah = s_pd[la * 25 + 3];
        box_corners(ax, ay, aw, ah, alx, aly, ahx, ahy, aar);
        const float a3 = aar * THIRD;

        // ---- screen: inter - br/3 >= aar/3  <=>  3*inter >= aar+br  <=>  iou >= 0.5
        // (CIoU <= IoU, so misses can never flip "max CIoU < 0.5".)
        // Single clamp on iw: if ih<0 then inter<=0 < (aar+br)/3, screen is
        // correctly false; on the hit path ih>0 is implied.
        const float4* gp = s_geo + j0;
        const float*  bp = s_b3  + j0;
        #pragma unroll 2
        for (int k = 0; k < CHUNK; k++) {
            float4 g  = gp[k];
            float  b3 = bp[k];
            float iw = fmaxf(fminf(ahx, g.z) - fmaxf(alx, g.x), 0.0f);
            float ih = fminf(ahy, g.w) - fmaxf(aly, g.y);
            float inter = iw * ih;
            if ((inter - b3) >= a3) {   // rare
                float4 aux = s_aux[j0 + k];
                float uni = aar + aux.w - inter;
                float iou = __fdividef(inter, fmaxf(uni, EPSY));
                float ow = fmaxf(ahx, g.z) - fminf(alx, g.x);
                float oh = fmaxf(ahy, g.w) - fminf(aly, g.y);
                float c2 = fmaxf(ow * ow + oh * oh, EPSY);
                float dx = ax - aux.x, dy = ay - aux.y;
                float u  = __fdividef(dx * dx + dy * dy, c2);
                float aat = atanf(__fdividef(aw, fmaxf(ah, EPSY)));
                float dv = aux.z - aat;
                float v  = INV_PI2 * dv * dv;
                float alpha = __fdividef(v, fmaxf(1.0f - iou + v, EPSY));
                m = fmaxf(m, iou - (u + alpha * v));
            }
        }
    }

    // combine max over the 4 sub-lanes (group-aligned)
    m = fmaxf(m, __shfl_xor_sync(full, m, 1));
    m = fmaxf(m, __shfl_xor_sync(full, m, 2));

    if (valid && sub == 0) {
        const float* lv = s_lb + la * 26;
        const float* pp = s_p  + la * 25;
        float lv0 = lv[0], lv1 = lv[1], lv2 = lv[2], lv3 = lv[3];
        float obj = lv[4], mix = lv[5];

        float glx, gly, ghx, ghy, gar;
        box_corners(lv0, lv1, lv2, lv3, glx, gly, ghx, ghy, gar);
        float gat = atanf(__fdividef(lv2, fmaxf(lv3, EPSY)));
        float aat = atanf(__fdividef(aw, fmaxf(ah, EPSY)));

        float ciou = ciou_full(alx, aly, ahx, ahy, aar, ax, ay, aat,
                               glx, gly, ghx, ghy, gar, lv0, lv1, gat);
        float scale = 2.0f - lv2 * lv3 * inv_img2;
        sum_ciou = obj * scale * (1.0f - ciou) * mix;

        float noobj = (1.0f - obj) * ((m < 0.5f) ? 1.0f : 0.0f);

        float pc  = pp[4];
        float bce = softplusf(pc) - pc * obj;
        float sg  = __fdividef(1.0f, 1.0f + expf(-pc));
        float d   = obj - sg;
        sum_conf = (obj + noobj) * (bce * d * d) * mix;   // ALPHA=1, GAMMA=2

        if (obj != 0.0f) {
            float cls = 0.0f;
            #pragma unroll
            for (int c = 0; c < NCLS; c++) {
                float xcl = pp[5 + c];
                float tcl = lv[6 + c];
                cls += softplusf(xcl) - xcl * tcl;
            }
            sum_cls = obj * mix * cls;
        }
    }

    // ---- block reduction ----
    #pragma unroll
    for (int off = 16; off > 0; off >>= 1) {
        sum_ciou += __shfl_down_sync(full, sum_ciou, off);
        sum_conf += __shfl_down_sync(full, sum_conf, off);
        sum_cls  += __shfl_down_sync(full, sum_cls,  off);
    }
    int lane = threadIdx.x & 31;
    int wid  = threadIdx.x >> 5;
    if (lane == 0) {
        s_red[0][wid] = sum_ciou;
        s_red[1][wid] = sum_conf;
        s_red[2][wid] = sum_cls;
    }
    __syncthreads();
    if (wid == 0) {
        float r0 = (lane < 8) ? s_red[0][lane] : 0.0f;
        float r1 = (lane < 8) ? s_red[1][lane] : 0.0f;
        float r2 = (lane < 8) ? s_red[2][lane] : 0.0f;
        #pragma unroll
        for (int off = 4; off > 0; off >>= 1) {
            r0 += __shfl_down_sync(full, r0, off);
            r1 += __shfl_down_sync(full, r1, off);
            r2 += __shfl_down_sync(full, r2, off);
        }
        if (lane == 0) {
            r0 *= inv_bs; r1 *= inv_bs; r2 *= inv_bs;
            atomicAdd(&out[1], r0);
            atomicAdd(&out[2], r1);
            atomicAdd(&out[3], r2);
            atomicAdd(&out[0], r0 + r1 + r2);
        }
    }
}

extern "C" void kernel_launch(void* const* d_in, const int* in_sizes, int n_in,
                              void* d_out, int out_size)
{
    // Identify tensors by element count (robust to metadata ordering).
    const int grids[3] = { 76, 38, 19 };
    const int B = 4, A = 3;

    const float* p[3]     = { 0, 0, 0 };
    const float* pd[3]    = { 0, 0, 0 };
    const float* label[3] = { 0, 0, 0 };
    const float* bbox[3]  = { 0, 0, 0 };

    int p_size[3], l_size[3];
    for (int l = 0; l < 3; l++) {
        int na = B * grids[l] * grids[l] * A;
        p_size[l] = na * 25;
        l_size[l] = na * 26;
    }

    int bbox_seen = 0;
    for (int i = 0; i < n_in; i++) {
        int sz = in_sizes[i];
        const float* ptr = (const float*)d_in[i];
        if (sz == B * 150 * 4) {
            if (bbox_seen < 3) bbox[bbox_seen++] = ptr;
            continue;
        }
        for (int l = 0; l < 3; l++) {
            if (sz == p_size[l]) {
                if (!p[l]) p[l] = ptr; else pd[l] = ptr;
                break;
            }
            if (sz == l_size[l]) { label[l] = ptr; break; }
        }
    }

    float* out = (float*)d_out;
    cudaMemsetAsync(out, 0, 4 * sizeof(float));

    const float inv_img2 = 1.0f / (608.0f * 608.0f);
    const float inv_bs = 1.0f / (float)B;

    yolo_fused_kernel<<<TOTAL_BLOCKS, 256>>>(
        p[0], p[1], p[2],
        pd[0], pd[1], pd[2],
        label[0], label[1], label[2],
        bbox[0], bbox[1], bbox[2],
        inv_img2, inv_bs, out);
}

// round 16
// speedup vs baseline: 1.0614x; 1.0614x over previous
#include <cuda_runtime.h>
#include <math_constants.h>

#define EPSY 1e-6f
#define NB 150
#define NBP 152              // padded: each sub-lane scans exactly 38
#define NCLS 20
#define INV_PI2 0.405284734569351f   // 4/pi^2
#define THIRD 0.3333333333333333f

// ---- fixed problem shape ----
#define BATCH 4
#define PB0 17328   // 76*76*3
#define PB1 4332    // 38*38*3
#define PB2 1083    // 19*19*3
#define SPLIT 4
#define APB 64              // anchors per block (256 threads / SPLIT)
#define NBLK0 271           // ceil(PB0/64)
#define NBLK1 68
#define NBLK2 17
#define CUM1 (NBLK0*BATCH)                 // 1084
#define CUM2 (CUM1 + NBLK1*BATCH)          // 1356
#define TOTAL_BLOCKS (CUM2 + NBLK2*BATCH)  // 1424
#define CHUNK 38            // NBP / SPLIT

// zero-initialized device accumulators (reset by the last block each launch,
// so every graph replay sees identical initial state)
__device__ float    g_acc[4] = {0.0f, 0.0f, 0.0f, 0.0f};
__device__ unsigned g_done   = 0u;

__device__ __forceinline__ float softplusf(float x) {
    return (x > 0.0f) ? (x + log1pf(expf(-x))) : log1pf(expf(x));
}

__device__ __forceinline__ void box_corners(
    float x, float y, float w, float h,
    float& lx, float& ly, float& hx, float& hy, float& ar)
{
    float ltx = x - w * 0.5f, rbx = x + w * 0.5f;
    float lty = y - h * 0.5f, rby = y + h * 0.5f;
    lx = fminf(ltx, rbx); hx = fmaxf(ltx, rbx);
    ly = fminf(lty, rby); hy = fmaxf(lty, rby);
    ar = (hx - lx) * (hy - ly);
}

// Full CIoU (reference-faithful, fast divides).
__device__ __forceinline__ float ciou_full(
    float alx, float aly, float ahx, float ahy, float aar, float acx, float acy, float aat,
    float blx, float bly, float bhx, float bhy, float bar, float bcx, float bcy, float bat)
{
    float iw = fminf(ahx, bhx) - fmaxf(alx, blx); iw = fmaxf(iw, 0.0f);
    float ih = fminf(ahy, bhy) - fmaxf(aly, bly); ih = fmaxf(ih, 0.0f);
    float inter = iw * ih;
    float uni   = aar + bar - inter;
    float iou   = __fdividef(inter, fmaxf(uni, EPSY));
    float ow = fmaxf(ahx, bhx) - fminf(alx, blx);
    float oh = fmaxf(ahy, bhy) - fminf(aly, bly);
    float c2 = fmaxf(ow * ow + oh * oh, EPSY);
    float dx = acx - bcx, dy = acy - bcy;
    float u  = __fdividef(dx * dx + dy * dy, c2);
    float dv = bat - aat;
    float v  = INV_PI2 * dv * dv;
    float alpha = __fdividef(v, fmaxf(1.0f - iou + v, EPSY));
    return iou - (u + alpha * v);
}

__global__ __launch_bounds__(256)
void yolo_fused_kernel(
    const float* __restrict__ p0,  const float* __restrict__ p1,  const float* __restrict__ p2,
    const float* __restrict__ pd0, const float* __restrict__ pd1, const float* __restrict__ pd2,
    const float* __restrict__ lb0, const float* __restrict__ lb1, const float* __restrict__ lb2,
    const float* __restrict__ bb0, const float* __restrict__ bb1, const float* __restrict__ bb2,
    float inv_img2, float inv_bs,
    float* __restrict__ out)
{
    __shared__ float4 s_geo[NBP];   // lx, ly, hx, hy
    __shared__ float  s_b3[NBP];    // area/3  (pad: +huge -> never hits)
    __shared__ float4 s_aux[NBP];   // cx, cy, atan(w/h), area
    __shared__ float  s_red[3][8];

    // ---- decode block -> (layer segment, batch, block-within-batch) ----
    int bid = blockIdx.x;
    int rem, nb, per_batch;
    const float *p, *pd, *lb, *bb;
    if (bid < CUM1)      { rem = bid;        nb = NBLK0; per_batch = PB0; p = p0; pd = pd0; lb = lb0; bb = bb0; }
    else if (bid < CUM2) { rem = bid - CUM1; nb = NBLK1; per_batch = PB1; p = p1; pd = pd1; lb = lb1; bb = bb1; }
    else                 { rem = bid - CUM2; nb = NBLK2; per_batch = PB2; p = p2; pd = pd2; lb = lb2; bb = bb2; }
    int b   = rem / nb;
    int blk = rem - b * nb;

    // ---- stage this batch's bboxes (preprocessed, padded) in smem ----
    for (int j = threadIdx.x; j < NBP; j += blockDim.x) {
        if (j < NB) {
            const float* q = bb + ((size_t)b * NB + j) * 4;
            float x = q[0], y = q[1], w = q[2], h = q[3];
            float lx, ly, hx, hy, ar;
            box_corners(x, y, w, h, lx, ly, hx, hy, ar);
            s_geo[j] = make_float4(lx, ly, hx, hy);
            s_b3[j]  = ar * THIRD;
            s_aux[j] = make_float4(x, y, atanf(__fdividef(w, fmaxf(h, EPSY))), ar);
        } else {
            s_geo[j] = make_float4(0.0f, 0.0f, 0.0f, 0.0f);
            s_b3[j]  = 3.0e30f;
            s_aux[j] = make_float4(0.0f, 0.0f, 0.0f, 1.0f);
        }
    }
    __syncthreads();

    const int sub = threadIdx.x & (SPLIT - 1);
    const int lane_anchor = threadIdx.x >> 2;   // 0..63
    const int j0 = sub * CHUNK;
    const unsigned full = 0xFFFFFFFFu;

    const int i = blk * APB + lane_anchor;
    const bool valid = (i < per_batch);

    float sum_ciou = 0.0f, sum_conf = 0.0f, sum_cls = 0.0f;
    float m = -CUDART_INF_F;

    float alx, aly, ahx, ahy, aar, ax, ay, aw, ah;
    float lv0 = 0, lv1 = 0, lv2 = 0, lv3 = 0, obj = 0, mix = 0, pc = 0;
    size_t idx = 0;

    if (valid) {
        idx = (size_t)b * per_batch + i;
        const float* pdp = pd + idx * 25;
        ax = pdp[0]; ay = pdp[1]; aw = pdp[2]; ah = pdp[3];

        // prefetch sub-0 epilogue scalars BEFORE the loop so their ~600cyc
        // DRAM latency hides under the 38-iteration screen.
        if (sub == 0) {
            const float* lv = lb + idx * 26;
            lv0 = lv[0]; lv1 = lv[1]; lv2 = lv[2]; lv3 = lv[3];
            obj = lv[4]; mix = lv[5];
            pc  = p[idx * 25 + 4];
        }

        box_corners(ax, ay, aw, ah, alx, aly, ahx, ahy, aar);
        const float a3 = aar * THIRD;

        // ---- screen: inter - br/3 >= aar/3  <=>  3*inter >= aar+br  <=>  iou >= 0.5
        // (CIoU <= IoU, so misses can never flip "max CIoU < 0.5".)
        // Single clamp on iw: if ih<0 then inter<=0 < (aar+br)/3, screen is
        // correctly false; on the hit path ih>0 is implied.
        const float4* gp = s_geo + j0;
        const float*  bp = s_b3  + j0;
        #pragma unroll 2
        for (int k = 0; k < CHUNK; k++) {
            float4 g  = gp[k];
            float  b3 = bp[k];
            float iw = fmaxf(fminf(ahx, g.z) - fmaxf(alx, g.x), 0.0f);
            float ih = fminf(ahy, g.w) - fmaxf(aly, g.y);
            float inter = iw * ih;
            if ((inter - b3) >= a3) {   // rare
                float4 aux = s_aux[j0 + k];
                float uni = aar + aux.w - inter;
                float iou = __fdividef(inter, fmaxf(uni, EPSY));
                float ow = fmaxf(ahx, g.z) - fminf(alx, g.x);
                float oh = fmaxf(ahy, g.w) - fminf(aly, g.y);
                float c2 = fmaxf(ow * ow + oh * oh, EPSY);
                float dx = ax - aux.x, dy = ay - aux.y;
                float u  = __fdividef(dx * dx + dy * dy, c2);
                float aat = atanf(__fdividef(aw, fmaxf(ah, EPSY)));
                float dv = aux.z - aat;
                float v  = INV_PI2 * dv * dv;
                float alpha = __fdividef(v, fmaxf(1.0f - iou + v, EPSY));
                m = fmaxf(m, iou - (u + alpha * v));
            }
        }
    }

    // combine max over the 4 sub-lanes (group-aligned)
    m = fmaxf(m, __shfl_xor_sync(full, m, 1));
    m = fmaxf(m, __shfl_xor_sync(full, m, 2));

    if (valid && sub == 0) {
        float glx, gly, ghx, ghy, gar;
        box_corners(lv0, lv1, lv2, lv3, glx, gly, ghx, ghy, gar);
        float gat = atanf(__fdividef(lv2, fmaxf(lv3, EPSY)));
        float aat = atanf(__fdividef(aw, fmaxf(ah, EPSY)));

        float ciou = ciou_full(alx, aly, ahx, ahy, aar, ax, ay, aat,
                               glx, gly, ghx, ghy, gar, lv0, lv1, gat);
        float scale = 2.0f - lv2 * lv3 * inv_img2;
        sum_ciou = obj * scale * (1.0f - ciou) * mix;

        float noobj = (1.0f - obj) * ((m < 0.5f) ? 1.0f : 0.0f);

        float bce = softplusf(pc) - pc * obj;
        float sg  = __fdividef(1.0f, 1.0f + expf(-pc));
        float d   = obj - sg;
        sum_conf = (obj + noobj) * (bce * d * d) * mix;   // ALPHA=1, GAMMA=2

        if (obj != 0.0f) {
            const float* pp = p  + idx * 25;
            const float* lv = lb + idx * 26;
            float cls = 0.0f;
            #pragma unroll
            for (int c = 0; c < NCLS; c++) {
                float xcl = pp[5 + c];
                float tcl = lv[6 + c];
                cls += softplusf(xcl) - xcl * tcl;
            }
            sum_cls = obj * mix * cls;
        }
    }

    // ---- block reduction ----
    #pragma unroll
    for (int off = 16; off > 0; off >>= 1) {
        sum_ciou += __shfl_down_sync(full, sum_ciou, off);
        sum_conf += __shfl_down_sync(full, sum_conf, off);
        sum_cls  += __shfl_down_sync(full, sum_cls,  off);
    }
    int lane = threadIdx.x & 31;
    int wid  = threadIdx.x >> 5;
    if (lane == 0) {
        s_red[0][wid] = sum_ciou;
        s_red[1][wid] = sum_conf;
        s_red[2][wid] = sum_cls;
    }
    __syncthreads();
    if (wid == 0) {
        float r0 = (lane < 8) ? s_red[0][lane] : 0.0f;
        float r1 = (lane < 8) ? s_red[1][lane] : 0.0f;
        float r2 = (lane < 8) ? s_red[2][lane] : 0.0f;
        #pragma unroll
        for (int off = 4; off > 0; off >>= 1) {
            r0 += __shfl_down_sync(full, r0, off);
            r1 += __shfl_down_sync(full, r1, off);
            r2 += __shfl_down_sync(full, r2, off);
        }
        if (lane == 0) {
            r0 *= inv_bs; r1 *= inv_bs; r2 *= inv_bs;
            atomicAdd(&g_acc[1], r0);
            atomicAdd(&g_acc[2], r1);
            atomicAdd(&g_acc[3], r2);
            atomicAdd(&g_acc[0], r0 + r1 + r2);
            __threadfence();
            unsigned ticket = atomicAdd(&g_done, 1u);
            if (ticket == (unsigned)(TOTAL_BLOCKS - 1)) {
                // last block: publish results and reset state for next replay
                float o0 = g_acc[0], o1 = g_acc[1], o2 = g_acc[2], o3 = g_acc[3];
                out[0] = o0; out[1] = o1; out[2] = o2; out[3] = o3;
                g_acc[0] = 0.0f; g_acc[1] = 0.0f; g_acc[2] = 0.0f; g_acc[3] = 0.0f;
                __threadfence();
                g_done = 0u;
            }
        }
    }
}

extern "C" void kernel_launch(void* const* d_in, const int* in_sizes, int n_in,
                              void* d_out, int out_size)
{
    // Identify tensors by element count (robust to metadata ordering).
    const int grids[3] = { 76, 38, 19 };
    const int B = 4, A = 3;

    const float* p[3]     = { 0, 0, 0 };
    const float* pd[3]    = { 0, 0, 0 };
    const float* label[3] = { 0, 0, 0 };
    const float* bbox[3]  = { 0, 0, 0 };

    int p_size[3], l_size[3];
    for (int l = 0; l < 3; l++) {
        int na = B * grids[l] * grids[l] * A;
        p_size[l] = na * 25;
        l_size[l] = na * 26;
    }

    int bbox_seen = 0;
    for (int i = 0; i < n_in; i++) {
        int sz = in_sizes[i];
        const float* ptr = (const float*)d_in[i];
        if (sz == B * 150 * 4) {
            if (bbox_seen < 3) bbox[bbox_seen++] = ptr;
            continue;
        }
        for (int l = 0; l < 3; l++) {
            if (sz == p_size[l]) {
                if (!p[l]) p[l] = ptr; else pd[l] = ptr;
                break;
            }
            if (sz == l_size[l]) { label[l] = ptr; break; }
        }
    }

    float* out = (float*)d_out;

    const float inv_img2 = 1.0f / (608.0f * 608.0f);
    const float inv_bs = 1.0f / (float)B;

    yolo_fused_kernel<<<TOTAL_BLOCKS, 256>>>(
        p[0], p[1], p[2],
        pd[0], pd[1], pd[2],
        label[0], label[1], label[2],
        bbox[0], bbox[1], bbox[2],
        inv_img2, inv_bs, out);
}

// round 17
// speedup vs baseline: 1.2703x; 1.1969x over previous
#include <cuda_runtime.h>
#include <math_constants.h>

#define EPSY 1e-6f
#define NB 150
#define NBP 152              // padded: each sub-lane scans exactly 38
#define NCLS 20
#define INV_PI2 0.405284734569351f   // 4/pi^2
#define THIRD 0.3333333333333333f

// ---- fixed problem shape ----
#define BATCH 4
#define PB0 17328   // 76*76*3
#define PB1 4332    // 38*38*3
#define PB2 1083    // 19*19*3
#define SPLIT 4
#define APB 64              // anchors per block (256 threads / SPLIT)
#define NBLK0 271           // ceil(PB0/64)
#define NBLK1 68
#define NBLK2 17
#define CUM1 (NBLK0*BATCH)                 // 1084
#define CUM2 (CUM1 + NBLK1*BATCH)          // 1356
#define TOTAL_BLOCKS (CUM2 + NBLK2*BATCH)  // 1424
#define CHUNK 38            // NBP / SPLIT

__device__ __forceinline__ float softplusf(float x) {
    return (x > 0.0f) ? (x + log1pf(expf(-x))) : log1pf(expf(x));
}

__device__ __forceinline__ void box_corners(
    float x, float y, float w, float h,
    float& lx, float& ly, float& hx, float& hy, float& ar)
{
    float ltx = x - w * 0.5f, rbx = x + w * 0.5f;
    float lty = y - h * 0.5f, rby = y + h * 0.5f;
    lx = fminf(ltx, rbx); hx = fmaxf(ltx, rbx);
    ly = fminf(lty, rby); hy = fmaxf(lty, rby);
    ar = (hx - lx) * (hy - ly);
}

// Full CIoU (reference-faithful, fast divides).
__device__ __forceinline__ float ciou_full(
    float alx, float aly, float ahx, float ahy, float aar, float acx, float acy, float aat,
    float blx, float bly, float bhx, float bhy, float bar, float bcx, float bcy, float bat)
{
    float iw = fminf(ahx, bhx) - fmaxf(alx, blx); iw = fmaxf(iw, 0.0f);
    float ih = fminf(ahy, bhy) - fmaxf(aly, bly); ih = fmaxf(ih, 0.0f);
    float inter = iw * ih;
    float uni   = aar + bar - inter;
    float iou   = __fdividef(inter, fmaxf(uni, EPSY));
    float ow = fmaxf(ahx, bhx) - fminf(alx, blx);
    float oh = fmaxf(ahy, bhy) - fminf(aly, bly);
    float c2 = fmaxf(ow * ow + oh * oh, EPSY);
    float dx = acx - bcx, dy = acy - bcy;
    float u  = __fdividef(dx * dx + dy * dy, c2);
    float dv = bat - aat;
    float v  = INV_PI2 * dv * dv;
    float alpha = __fdividef(v, fmaxf(1.0f - iou + v, EPSY));
    return iou - (u + alpha * v);
}

__global__ __launch_bounds__(256)
void yolo_fused_kernel(
    const float* __restrict__ p0,  const float* __restrict__ p1,  const float* __restrict__ p2,
    const float* __restrict__ pd0, const float* __restrict__ pd1, const float* __restrict__ pd2,
    const float* __restrict__ lb0, const float* __restrict__ lb1, const float* __restrict__ lb2,
    const float* __restrict__ bb0, const float* __restrict__ bb1, const float* __restrict__ bb2,
    float inv_img2, float inv_bs,
    float* __restrict__ out)
{
    __shared__ float4 s_geo[NBP];   // lx, ly, hx, hy
    __shared__ float  s_b3[NBP];    // area/3  (pad: +huge -> never hits)
    __shared__ float4 s_aux[NBP];   // cx, cy, atan(w/h), area
    __shared__ float  s_red[3][8];

    // ---- decode block -> (layer segment, batch, block-within-batch) ----
    int bid = blockIdx.x;
    int rem, nb, per_batch;
    const float *p, *pd, *lb, *bb;
    if (bid < CUM1)      { rem = bid;        nb = NBLK0; per_batch = PB0; p = p0; pd = pd0; lb = lb0; bb = bb0; }
    else if (bid < CUM2) { rem = bid - CUM1; nb = NBLK1; per_batch = PB1; p = p1; pd = pd1; lb = lb1; bb = bb1; }
    else                 { rem = bid - CUM2; nb = NBLK2; per_batch = PB2; p = p2; pd = pd2; lb = lb2; bb = bb2; }
    int b   = rem / nb;
    int blk = rem - b * nb;

    // ---- stage this batch's bboxes (preprocessed, padded) in smem ----
    for (int j = threadIdx.x; j < NBP; j += blockDim.x) {
        if (j < NB) {
            const float* q = bb + ((size_t)b * NB + j) * 4;
            float x = q[0], y = q[1], w = q[2], h = q[3];
            float lx, ly, hx, hy, ar;
            box_corners(x, y, w, h, lx, ly, hx, hy, ar);
            s_geo[j] = make_float4(lx, ly, hx, hy);
            s_b3[j]  = ar * THIRD;
            s_aux[j] = make_float4(x, y, atanf(__fdividef(w, fmaxf(h, EPSY))), ar);
        } else {
            s_geo[j] = make_float4(0.0f, 0.0f, 0.0f, 0.0f);
            s_b3[j]  = 3.0e30f;
            s_aux[j] = make_float4(0.0f, 0.0f, 0.0f, 1.0f);
        }
    }
    __syncthreads();

    const int sub = threadIdx.x & (SPLIT - 1);
    const int lane_anchor = threadIdx.x >> 2;   // 0..63
    const int j0 = sub * CHUNK;
    const unsigned full = 0xFFFFFFFFu;

    const int i = blk * APB + lane_anchor;
    const bool valid = (i < per_batch);

    float sum_ciou = 0.0f, sum_conf = 0.0f, sum_cls = 0.0f;
    float m = -CUDART_INF_F;

    float alx, aly, ahx, ahy, aar, ax, ay, aw, ah;
    float lv0 = 0, lv1 = 0, lv2 = 0, lv3 = 0, obj = 0, mix = 0, pc = 0;
    size_t idx = 0;

    if (valid) {
        idx = (size_t)b * per_batch + i;
        const float* pdp = pd + idx * 25;
        ax = pdp[0]; ay = pdp[1]; aw = pdp[2]; ah = pdp[3];

        // prefetch epilogue scalars BEFORE the loop so their ~600cyc DRAM
        // latency hides under the 38-iteration screen. obj/mix on ALL
        // sub-lanes (same-address broadcast) to gate the distributed cls loop.
        {
            const float* lv = lb + idx * 26;
            obj = lv[4]; mix = lv[5];
            if (sub == 0) {
                lv0 = lv[0]; lv1 = lv[1]; lv2 = lv[2]; lv3 = lv[3];
                pc  = p[idx * 25 + 4];
            }
        }

        box_corners(ax, ay, aw, ah, alx, aly, ahx, ahy, aar);
        const float a3 = aar * THIRD;

        // ---- screen: inter - br/3 >= aar/3  <=>  3*inter >= aar+br  <=>  iou >= 0.5
        // (CIoU <= IoU, so misses can never flip "max CIoU < 0.5".)
        // Single clamp on iw: if ih<0 then inter<=0 < (aar+br)/3, screen is
        // correctly false; on the hit path ih>0 is implied.
        const float4* gp = s_geo + j0;
        const float*  bp = s_b3  + j0;
        #pragma unroll 2
        for (int k = 0; k < CHUNK; k++) {
            float4 g  = gp[k];
            float  b3 = bp[k];
            float iw = fmaxf(fminf(ahx, g.z) - fmaxf(alx, g.x), 0.0f);
            float ih = fminf(ahy, g.w) - fmaxf(aly, g.y);
            float inter = iw * ih;
            if ((inter - b3) >= a3) {   // rare
                float4 aux = s_aux[j0 + k];
                float uni = aar + aux.w - inter;
                float iou = __fdividef(inter, fmaxf(uni, EPSY));
                float ow = fmaxf(ahx, g.z) - fminf(alx, g.x);
                float oh = fmaxf(ahy, g.w) - fminf(aly, g.y);
                float c2 = fmaxf(ow * ow + oh * oh, EPSY);
                float dx = ax - aux.x, dy = ay - aux.y;
                float u  = __fdividef(dx * dx + dy * dy, c2);
                float aat = atanf(__fdividef(aw, fmaxf(ah, EPSY)));
                float dv = aux.z - aat;
                float v  = INV_PI2 * dv * dv;
                float alpha = __fdividef(v, fmaxf(1.0f - iou + v, EPSY));
                m = fmaxf(m, iou - (u + alpha * v));
            }
        }
    }

    // combine max over the 4 sub-lanes (group-aligned)
    m = fmaxf(m, __shfl_xor_sync(full, m, 1));
    m = fmaxf(m, __shfl_xor_sync(full, m, 2));

    // ---- distributed cls epilogue: each sub-lane takes 5 of the 20 classes.
    // Partial sums flow into the block reduction (sum over all threads), so
    // no extra combine is needed. 4x the load MLP, 4x shorter softplus chain.
    if (valid && obj != 0.0f) {
        const float* pp = p  + idx * 25;
        const float* lv = lb + idx * 26;
        float cls = 0.0f;
        #pragma unroll
        for (int c = sub; c < NCLS; c += SPLIT) {
            float xcl = pp[5 + c];
            float tcl = lv[6 + c];
            cls += softplusf(xcl) - xcl * tcl;
        }
        sum_cls = obj * mix * cls;
    }

    if (valid && sub == 0) {
        float glx, gly, ghx, ghy, gar;
        box_corners(lv0, lv1, lv2, lv3, glx, gly, ghx, ghy, gar);
        float gat = atanf(__fdividef(lv2, fmaxf(lv3, EPSY)));
        float aat = atanf(__fdividef(aw, fmaxf(ah, EPSY)));

        float ciou = ciou_full(alx, aly, ahx, ahy, aar, ax, ay, aat,
                               glx, gly, ghx, ghy, gar, lv0, lv1, gat);
        float scale = 2.0f - lv2 * lv3 * inv_img2;
        sum_ciou = obj * scale * (1.0f - ciou) * mix;

        float noobj = (1.0f - obj) * ((m < 0.5f) ? 1.0f : 0.0f);

        float bce = softplusf(pc) - pc * obj;
        float sg  = __fdividef(1.0f, 1.0f + expf(-pc));
        float d   = obj - sg;
        sum_conf = (obj + noobj) * (bce * d * d) * mix;   // ALPHA=1, GAMMA=2
    }

    // ---- block reduction ----
    #pragma unroll
    for (int off = 16; off > 0; off >>= 1) {
        sum_ciou += __shfl_down_sync(full, sum_ciou, off);
        sum_conf += __shfl_down_sync(full, sum_conf, off);
        sum_cls  += __shfl_down_sync(full, sum_cls,  off);
    }
    int lane = threadIdx.x & 31;
    int wid  = threadIdx.x >> 5;
    if (lane == 0) {
        s_red[0][wid] = sum_ciou;
        s_red[1][wid] = sum_conf;
        s_red[2][wid] = sum_cls;
    }
    __syncthreads();
    if (wid == 0) {
        float r0 = (lane < 8) ? s_red[0][lane] : 0.0f;
        float r1 = (lane < 8) ? s_red[1][lane] : 0.0f;
        float r2 = (lane < 8) ? s_red[2][lane] : 0.0f;
        #pragma unroll
        for (int off = 4; off > 0; off >>= 1) {
            r0 += __shfl_down_sync(full, r0, off);
            r1 += __shfl_down_sync(full, r1, off);
            r2 += __shfl_down_sync(full, r2, off);
        }
        if (lane == 0) {
            r0 *= inv_bs; r1 *= inv_bs; r2 *= inv_bs;
            atomicAdd(&out[1], r0);
            atomicAdd(&out[2], r1);
            atomicAdd(&out[3], r2);
            atomicAdd(&out[0], r0 + r1 + r2);
        }
    }
}

extern "C" void kernel_launch(void* const* d_in, const int* in_sizes, int n_in,
                              void* d_out, int out_size)
{
    // Identify tensors by element count (robust to metadata ordering).
    const int grids[3] = { 76, 38, 19 };
    const int B = 4, A = 3;

    const float* p[3]     = { 0, 0, 0 };
    const float* pd[3]    = { 0, 0, 0 };
    const float* label[3] = { 0, 0, 0 };
    const float* bbox[3]  = { 0, 0, 0 };

    int p_size[3], l_size[3];
    for (int l = 0; l < 3; l++) {
        int na = B * grids[l] * grids[l] * A;
        p_size[l] = na * 25;
        l_size[l] = na * 26;
    }

    int bbox_seen = 0;
    for (int i = 0; i < n_in; i++) {
        int sz = in_sizes[i];
        const float* ptr = (const float*)d_in[i];
        if (sz == B * 150 * 4) {
            if (bbox_seen < 3) bbox[bbox_seen++] = ptr;
            continue;
        }
        for (int l = 0; l < 3; l++) {
            if (sz == p_size[l]) {
                if (!p[l]) p[l] = ptr; else pd[l] = ptr;
                break;
            }
            if (sz == l_size[l]) { label[l] = ptr; break; }
        }
    }

    float* out = (float*)d_out;
    cudaMemsetAsync(out, 0, 4 * sizeof(float));

    const float inv_img2 = 1.0f / (608.0f * 608.0f);
    const float inv_bs = 1.0f / (float)B;

    yolo_fused_kernel<<<TOTAL_BLOCKS, 256>>>(
        p[0], p[1], p[2],
        pd[0], pd[1], pd[2],
        label[0], label[1], label[2],
        bbox[0], bbox[1], bbox[2],
        inv_img2, inv_bs, out);
}